// round 9
// baseline (speedup 1.0000x reference)
#include <cuda_runtime.h>
#include <stdint.h>

#define NCOMP 256
#define PPB   8     // pairs per block
#define TPB   512   // two j-halves x 256 components

__global__ __launch_bounds__(TPB, 1) void clifford_kernel(
    const float* __restrict__ A, const float* __restrict__ B,
    float* __restrict__ out, int npairs)
{
    // 40 KB pool:
    //   [0KB)  As0  float4[256]  pairs 0..3 of A at component j
    //   [4KB)  As1  float4[256]  pairs 4..7
    //   [8KB)  Bp0/Bp1           B positive copies
    //   [16KB) Bn0/Bn1           B negated copies
    //   [24KB) Ssh  sign table (8KB)  -- reused as Red after the loop
    //   [32KB) Ish  inner table (8KB)
    __shared__ __align__(16) unsigned char pool[40960];
    float4*   As0 = reinterpret_cast<float4*>(pool);
    float4*   As1 = reinterpret_cast<float4*>(pool + 4096);
    uint32_t* Ssh = reinterpret_cast<uint32_t*>(pool + 24576);
    uint32_t* Ish = reinterpret_cast<uint32_t*>(pool + 32768);
    float4*   Red = reinterpret_cast<float4*>(pool + 24576);

    const int tid  = threadIdx.x;
    const int half = tid >> 8;       // 0: j in [0,128)   1: j in [128,256)
    const int i    = tid & 255;      // output component owned by this thread
    const int p0   = blockIdx.x * PPB;

    // ---- issue gmem loads first (long latency, overlap with table build) ----
    const float* Ap = A + (size_t)(p0 + 4 * half) * NCOMP + i;
    const float* Bp = B + (size_t)(p0 + 4 * half) * NCOMP + i;
    float4 va, vb;
    va.x = Ap[0 * NCOMP]; va.y = Ap[1 * NCOMP]; va.z = Ap[2 * NCOMP]; va.w = Ap[3 * NCOMP];
    vb.x = Bp[0 * NCOMP]; vb.y = Bp[1 * NCOMP]; vb.z = Bp[2 * NCOMP]; vb.w = Bp[3 * NCOMP];

    // ---- build sign + inner tables in closed form (4 words each per thread) ----
    {
        const int j   = tid & 255;
        const int h   = (j >> 1) ^ (j >> 2) ^ (j >> 3) ^ (j >> 4) ^ (j >> 5) ^ (j >> 6) ^ (j >> 7);
        const int P1  = __popc(j & h) & 1;
        const int h5  = h >> 5;
        const int jlo = j & 31, jhi = j >> 5;
        // Walsh pattern: bit L = parity(L & (h & 31))
        uint32_t W = 0;
        if (h & 1)  W ^= 0xAAAAAAAAu;
        if (h & 2)  W ^= 0xCCCCCCCCu;
        if (h & 4)  W ^= 0xF0F0F0F0u;
        if (h & 8)  W ^= 0xFF00FF00u;
        if (h & 16) W ^= 0xFFFF0000u;
        // Mz: bit L = 1 iff (L & jlo) == 0
        uint32_t Mz = 0xFFFFFFFFu;
        if (jlo & 1)  Mz &= 0x55555555u;
        if (jlo & 2)  Mz &= 0x33333333u;
        if (jlo & 4)  Mz &= 0x0F0F0F0Fu;
        if (jlo & 8)  Mz &= 0x00FF00FFu;
        if (jlo & 16) Mz &= 0x0000FFFFu;
        // Ms: bit L = 1 iff (L & ~jlo) == 0  (L subset of jlo)
        const int nj = ~jlo & 31;
        uint32_t Ms = 0xFFFFFFFFu;
        if (nj & 1)  Ms &= 0x55555555u;
        if (nj & 2)  Ms &= 0x33333333u;
        if (nj & 4)  Ms &= 0x0F0F0F0Fu;
        if (nj & 8)  Ms &= 0x00FF00FFu;
        if (nj & 16) Ms &= 0x0000FFFFu;
#pragma unroll
        for (int q = 0; q < 4; ++q) {
            const int ihi = ((tid >> 8) << 2) + q;
            const int c   = P1 ^ (__popc(ihi & h5) & 1);
            Ssh[(ihi << 8) + j] = c ? ~W : W;
            uint32_t iw = 0;
            if ((jhi & ihi) == 0)      iw |= Mz;   // (j & i) == 0
            if ((ihi & ~jhi & 7) == 0) iw |= Ms;   // i subset of j
            Ish[(ihi << 8) + j] = iw;
        }
    }

    // ---- stage A / B(+) / B(-) pair-split ----
    {
        float4 vn;
        vn.x = -vb.x; vn.y = -vb.y; vn.z = -vb.z; vn.w = -vb.w;
        *reinterpret_cast<float4*>(pool + (half ? 4096 : 0) + i * 16)         = va;
        *reinterpret_cast<float4*>(pool + 8192  + (half ? 4096 : 0) + i * 16) = vb;
        *reinterpret_cast<float4*>(pool + 16384 + (half ? 4096 : 0) + i * 16) = vn;
    }
    __syncthreads();

    const int lane  = i & 31;
    const int shamt = 31 - lane;
    const int notI  = (~i) & 255;
    const int ihiw  = i >> 5;                 // warp-uniform
    const uint32_t* __restrict__ Srow = Ssh + (ihiw << 8);
    const uint32_t* __restrict__ Irow = Ish + (ihiw << 8);
    const int jbase = half << 7;

    float g0=0.f,g1=0.f,g2=0.f,g3=0.f,g4=0.f,g5=0.f,g6=0.f,g7=0.f;   // geometric
    float w0=0.f,w1=0.f,w2=0.f,w3=0.f,w4=0.f,w5=0.f,w6=0.f,w7=0.f;   // wedge
    float n0=0.f,n1=0.f,n2=0.f,n3=0.f,n4=0.f,n5=0.f,n6=0.f,n7=0.f;   // inner

#define DO_J(JOFF, SW, ID, WED, INN)                                            \
        {                                                                       \
            const int      jj  = jb + (JOFF);                                   \
            const int      kx  = jj ^ i;                                        \
            const uint32_t boff = (((int)((SW) << shamt) < 0) ? 16384u : 8192u) \
                                  + (uint32_t)(kx << 4);                        \
            const float4 a0 = As0[jj];                                          \
            const float4 a1 = As1[jj];                                          \
            const float4 b0 = *reinterpret_cast<const float4*>(pool + boff);    \
            const float4 b1 = *reinterpret_cast<const float4*>(pool + boff + 4096); \
            g0 = fmaf(a0.x, b0.x, g0); g1 = fmaf(a0.y, b0.y, g1);               \
            g2 = fmaf(a0.z, b0.z, g2); g3 = fmaf(a0.w, b0.w, g3);               \
            g4 = fmaf(a1.x, b1.x, g4); g5 = fmaf(a1.y, b1.y, g5);               \
            g6 = fmaf(a1.z, b1.z, g6); g7 = fmaf(a1.w, b1.w, g7);               \
            if (WED) {                                                          \
                if ((jj & notI) == 0) {                                         \
                    w0 = fmaf(a0.x, b0.x, w0); w1 = fmaf(a0.y, b0.y, w1);       \
                    w2 = fmaf(a0.z, b0.z, w2); w3 = fmaf(a0.w, b0.w, w3);       \
                    w4 = fmaf(a1.x, b1.x, w4); w5 = fmaf(a1.y, b1.y, w5);       \
                    w6 = fmaf(a1.z, b1.z, w6); w7 = fmaf(a1.w, b1.w, w7);       \
                }                                                               \
            }                                                                   \
            if (INN) {                                                          \
                if ((int)((ID) << shamt) < 0) {                                 \
                    n0 = fmaf(a0.x, b0.x, n0); n1 = fmaf(a0.y, b0.y, n1);       \
                    n2 = fmaf(a0.z, b0.z, n2); n3 = fmaf(a0.w, b0.w, n3);       \
                    n4 = fmaf(a1.x, b1.x, n4); n5 = fmaf(a1.y, b1.y, n5);       \
                    n6 = fmaf(a1.z, b1.z, n6); n7 = fmaf(a1.w, b1.w, n7);       \
                }                                                               \
            }                                                                   \
        }

#define GROUP_LOOP(WED, INN)                                                    \
        _Pragma("unroll 2")                                                     \
        for (int t4 = 0; t4 < 8; ++t4) {                                        \
            const int jb = gbase + (t4 << 2);                                   \
            const uint4 s4 = *reinterpret_cast<const uint4*>(Srow + jb);        \
            uint4 i4 = make_uint4(0u, 0u, 0u, 0u);                              \
            if (INN) i4 = *reinterpret_cast<const uint4*>(Irow + jb);           \
            DO_J(0, s4.x, i4.x, WED, INN)                                       \
            DO_J(1, s4.y, i4.y, WED, INN)                                       \
            DO_J(2, s4.z, i4.z, WED, INN)                                       \
            DO_J(3, s4.w, i4.w, WED, INN)                                       \
        }

#pragma unroll 1
    for (int g = 0; g < 4; ++g) {
        const int gbase = jbase + (g << 5);
        const int jg    = gbase >> 5;                       // warp-uniform group high bits
        const bool wposs = ((jg & ~ihiw & 7) == 0);                         // any wedge lane?
        const bool iposs = ((jg & ihiw) == 0) || ((ihiw & ~jg & 7) == 0);   // any inner lane?
        if (wposs) {
            if (iposs) { GROUP_LOOP(1, 1) } else { GROUP_LOOP(1, 0) }
        } else {
            if (iposs) { GROUP_LOOP(0, 1) } else { GROUP_LOOP(0, 0) }
        }
    }
#undef GROUP_LOOP
#undef DO_J

    // ---- cross-half reduction (Red reuses the sign-table smem) + store ----
    __syncthreads();

    const size_t plane = (size_t)npairs * NCOMP;
    float* __restrict__ og = out + (size_t)p0 * NCOMP + i;

#define ROUND(V0,V1,V2,V3,V4,V5,V6,V7, DST)                                     \
    {                                                                           \
        if (half) {                                                             \
            Red[i * 2 + 0] = make_float4(V0, V1, V2, V3);                       \
            Red[i * 2 + 1] = make_float4(V4, V5, V6, V7);                       \
        }                                                                       \
        __syncthreads();                                                        \
        if (!half) {                                                            \
            const float4 r0 = Red[i * 2 + 0];                                   \
            const float4 r1 = Red[i * 2 + 1];                                   \
            (DST)[0 * NCOMP] = V0 + r0.x; (DST)[1 * NCOMP] = V1 + r0.y;         \
            (DST)[2 * NCOMP] = V2 + r0.z; (DST)[3 * NCOMP] = V3 + r0.w;         \
            (DST)[4 * NCOMP] = V4 + r1.x; (DST)[5 * NCOMP] = V5 + r1.y;         \
            (DST)[6 * NCOMP] = V6 + r1.z; (DST)[7 * NCOMP] = V7 + r1.w;         \
        }                                                                       \
        __syncthreads();                                                        \
    }

    ROUND(g0,g1,g2,g3,g4,g5,g6,g7, og)
    ROUND(w0,w1,w2,w3,w4,w5,w6,w7, og + plane)
    ROUND(n0,n1,n2,n3,n4,n5,n6,n7, og + 2 * plane)
#undef ROUND
}

extern "C" void kernel_launch(void* const* d_in, const int* in_sizes, int n_in,
                              void* d_out, int out_size)
{
    const float* A = (const float*)d_in[0];
    const float* B = (const float*)d_in[1];
    float* out = (float*)d_out;

    const int npairs = in_sizes[0] / NCOMP;   // 1024

    clifford_kernel<<<npairs / PPB, TPB>>>(A, B, out, npairs);
}